// round 2
// baseline (speedup 1.0000x reference)
#include <cuda_runtime.h>
#include <math.h>

#define DD   256
#define BB   8
#define CHK  64
#define NC   64
#define TLEN 4096

#define SA     260              // padded row stride for 32x256 / 64x256 smem tiles
#define SBT    33               // padded stride for B^T tile [j][cc]
#define SBN    260              // padded stride for B tile [cc][j]
#define TILE32 (32*SA)          // 8320 floats
#define BTSZ   (256*SBT)        // 8448 floats (>= 32*SBN)

// ---------------- persistent state (double-buffered) ----------------
// states: 0=k 1=v 2=q 3=eta 4=alpha 5=mem ; full-w1 index: k,v,q,mem -> 0,1,2,3
static __device__ float S_w1f[2][4][BB][DD*DD];
static __device__ float S_w2 [2][6][BB][DD*DD];
static __device__ float S_w1v[2][2][BB][DD];
static __device__ float S_wsk[2][2][BB][DD];

// ---------------- per-chunk scratch ----------------
static __device__ float SC_k [BB][CHK*DD];
static __device__ float SC_v [BB][CHK*DD];
static __device__ float SC_q [BB][CHK*DD];
static __device__ float SC_h2[6][BB][CHK*DD];
static __device__ float SC_g [4][BB][CHK*DD];
static __device__ float SC_pre[6][BB][CHK*DD];
static __device__ float SC_eta[BB][CHK];
static __device__ float SC_alpha[BB][CHK];
static __device__ float SC_vsum[BB][CHK];
static __device__ float SC_gs[2][BB][CHK];
static __device__ float SC_abar[BB];

// ---------------- math helpers ----------------
__device__ __forceinline__ float geluf(float z){
    return 0.5f*z*(1.0f + erff(z*0.70710678118654752f));
}
__device__ __forceinline__ float dgeluf(float z){
    float cdf = 0.5f*(1.0f + erff(z*0.70710678118654752f));
    float pdf = expf(-0.5f*z*z)*0.39894228040143267f;
    return cdf + z*pdf;
}
__device__ __forceinline__ float warp_sum(float v){
    #pragma unroll
    for(int o=16;o>0;o>>=1) v += __shfl_xor_sync(0xffffffffu, v, o);
    return v;
}

// load 32x256 global (row stride 256) -> smem tile (row stride SA)
__device__ __forceinline__ void load_tile32(float* dst, const float* __restrict__ src){
    const int tid = threadIdx.x;
    #pragma unroll
    for(int l=0;l<8;l++){
        int idx = tid + l*256;          // 0..2047 float4s
        int r = idx>>6, qc = (idx&63)<<2;
        float4 v = *reinterpret_cast<const float4*>(src + r*DD + qc);
        *reinterpret_cast<float4*>(dst + r*SA + qc) = v;
    }
}

// OUT[t,j] (t:32 rows, j:256) = sum_c A[t,c] * (TB ? B[j,c] : B[c,j]), c over 256.
// A in smem (stride SA), B in global 256x256 row-major, Bt is smem staging.
// Thread map: ty=tid/32 -> rows ty*4..+3 ; tx=tid%32 -> cols tx+jj*32.
template<int TB>
__device__ __forceinline__ void gemm32(const float* As, const float* __restrict__ Bg,
                                       float* Bt, float (&acc)[4][8]){
    const int tid = threadIdx.x, ty = tid>>5, tx = tid&31;
    #pragma unroll
    for(int r=0;r<4;r++)
        #pragma unroll
        for(int j=0;j<8;j++) acc[r][j] = 0.f;

    for(int c0=0;c0<DD;c0+=32){
        if(TB){
            // stage B[j][c0..c0+31] -> Bt[j*SBT + cc]
            #pragma unroll
            for(int l=0;l<8;l++){
                int idx = tid + l*256;                 // 2048 float4s
                int j = idx>>3, qc = (idx&7)<<2;
                float4 v = *reinterpret_cast<const float4*>(Bg + j*DD + c0 + qc);
                float* p = Bt + j*SBT + qc;
                p[0]=v.x; p[1]=v.y; p[2]=v.z; p[3]=v.w;
            }
        } else {
            // stage B[c0+cc][j] -> Bt[cc*SBN + j]
            #pragma unroll
            for(int l=0;l<8;l++){
                int idx = tid + l*256;
                int cc = idx>>6, qc = (idx&63)<<2;
                float4 v = *reinterpret_cast<const float4*>(Bg + (c0+cc)*DD + qc);
                *reinterpret_cast<float4*>(Bt + cc*SBN + qc) = v;
            }
        }
        __syncthreads();
        #pragma unroll 8
        for(int cc=0;cc<32;cc++){
            float a0 = As[(ty*4+0)*SA + c0+cc];
            float a1 = As[(ty*4+1)*SA + c0+cc];
            float a2 = As[(ty*4+2)*SA + c0+cc];
            float a3 = As[(ty*4+3)*SA + c0+cc];
            #pragma unroll
            for(int j=0;j<8;j++){
                float bv = TB ? Bt[(tx+j*32)*SBT + cc] : Bt[cc*SBN + tx + j*32];
                acc[0][j] = fmaf(a0,bv,acc[0][j]);
                acc[1][j] = fmaf(a1,bv,acc[1][j]);
                acc[2][j] = fmaf(a2,bv,acc[2][j]);
                acc[3][j] = fmaf(a3,bv,acc[3][j]);
            }
        }
        __syncthreads();
    }
}

// ---------------- K0: initialize per-batch state from inputs ----------------
__global__ void k0_init(const float* __restrict__ k1w, const float* __restrict__ k2w,
                        const float* __restrict__ v1w, const float* __restrict__ v2w,
                        const float* __restrict__ q1w, const float* __restrict__ q2w,
                        const float* __restrict__ e1w, const float* __restrict__ e2w,
                        const float* __restrict__ esw, const float* __restrict__ a1w,
                        const float* __restrict__ a2w, const float* __restrict__ asw,
                        const float* __restrict__ m1w, const float* __restrict__ m2w){
    const int gid = blockIdx.x*blockDim.x + threadIdx.x;   // 0..65535
    const int m = blockIdx.y;
    if(m<4){
        const float* src = (m==0)?k1w:(m==1)?v1w:(m==2)?q1w:m1w;
        float v = src[gid];
        #pragma unroll
        for(int b=0;b<BB;b++) S_w1f[0][m][b][gid] = v;
    } else if(m<10){
        const int s = m-4;
        const float* src = (s==0)?k2w:(s==1)?v2w:(s==2)?q2w:(s==3)?e2w:(s==4)?a2w:m2w;
        float v = src[gid];
        #pragma unroll
        for(int b=0;b<BB;b++) S_w2[0][s][b][gid] = v;
    } else {
        if(gid < DD){
            #pragma unroll
            for(int b=0;b<BB;b++){
                S_w1v[0][0][b][gid] = e1w[gid];
                S_w1v[0][1][b][gid] = a1w[gid];
                S_wsk[0][0][b][gid] = esw[gid];
                S_wsk[0][1][b][gid] = asw[gid];
            }
        }
    }
}

// ---------------- K1: forwards k,v,q,eta,alpha  (grid 80) ----------------
__global__ void __launch_bounds__(256) k1_forward(const float* __restrict__ x, int chunk){
    extern __shared__ float smem_[];
    float* Xs = smem_;
    float* Hs = smem_ + TILE32;
    float* Bt = smem_ + 2*TILE32;
    const int tid = threadIdx.x, ty = tid>>5, tx = tid&31;
    const int bx = blockIdx.x;
    const int th = bx&1, t2 = bx>>1, s = t2%5, b = t2/5;
    const int cur = chunk&1;
    const int tok0 = chunk*CHK + th*32;

    load_tile32(Xs, x + ((size_t)b*TLEN + tok0)*DD);
    __syncthreads();

    float acc[4][8];
    gemm32<1>(Xs, S_w2[cur][s][b], Bt, acc);

    float hreg[4][8];
    #pragma unroll
    for(int r=0;r<4;r++)
        #pragma unroll
        for(int j=0;j<8;j++){
            float h = geluf(acc[r][j]);
            hreg[r][j] = h;
            if(s<3) Hs[(ty*4+r)*SA + tx + j*32] = h;
        }

    if(s<3){
        gemm32<1>(Hs, S_w1f[cur][s][b], Bt, acc);
        #pragma unroll
        for(int r=0;r<4;r++){
            const int row = th*32 + ty*4 + r;
            float out[8]; float ss=0.f, vs=0.f;
            #pragma unroll
            for(int j=0;j<8;j++){
                const int col = tx + j*32;
                float o = Xs[(ty*4+r)*SA + col] + acc[r][j];
                out[j]=o; ss += o*o; vs += o;
            }
            if(s==1){
                vs = warp_sum(vs);
                #pragma unroll
                for(int j=0;j<8;j++) SC_v[b][row*DD + tx + j*32] = out[j];
                if(tx==0) SC_vsum[b][row] = vs;
            } else {
                ss = warp_sum(ss);
                float inv = 1.f / fmaxf(sqrtf(ss), 1e-6f);
                float* dst = (s==0)? SC_k[b] : SC_q[b];
                #pragma unroll
                for(int j=0;j<8;j++) dst[row*DD + tx + j*32] = out[j]*inv;
            }
        }
    } else {
        const int si = s-3;
        const float* wsk = S_wsk[cur][si][b];
        const float* w1v = S_w1v[cur][si][b];
        #pragma unroll
        for(int r=0;r<4;r++){
            const int row = th*32 + ty*4 + r;
            float p = 0.f;
            #pragma unroll
            for(int j=0;j<8;j++){
                const int col = tx + j*32;
                p += Xs[(ty*4+r)*SA + col]*wsk[col] + hreg[r][j]*w1v[col];
            }
            p = warp_sum(p);
            if(tx==0){
                if(s==3){ float sp = (p>20.f)? p : log1pf(expf(p)); SC_eta[b][row] = sp*0.001f; }
                else      SC_alpha[b][row] = 1.f/(1.f+expf(-p));
            }
        }
    }
}

// ---------------- K2: per-token update terms + output o  (grid 112) ----------------
__global__ void __launch_bounds__(256) k2_token(float* __restrict__ dout, int chunk){
    extern __shared__ float smem_[];
    const int tid = threadIdx.x, ty = tid>>5, tx = tid&31;
    const int bx = blockIdx.x;
    const int cur = chunk&1;

    if(bx < 64){
        // full-state (k,v,q,mem) per-token update pieces
        float* Ks = smem_;
        float* Hs = smem_ + TILE32;
        float* Gs = smem_ + 2*TILE32;
        float* Bt = smem_ + 3*TILE32;
        const int th = bx&1, t2 = bx>>1, f = t2&3, b = t2>>2;
        const int s = (f==3)? 5 : f;

        load_tile32(Ks, SC_k[b] + th*32*DD);
        __syncthreads();

        float acc[4][8], zreg[4][8];
        gemm32<1>(Ks, S_w2[cur][s][b], Bt, acc);
        #pragma unroll
        for(int r=0;r<4;r++)
            #pragma unroll
            for(int j=0;j<8;j++){
                float z = acc[r][j]; zreg[r][j] = z;
                float h = geluf(z);
                Hs[(ty*4+r)*SA + tx + j*32] = h;
                SC_h2[s][b][(th*32+ty*4+r)*DD + tx + j*32] = h;
            }
        gemm32<1>(Hs, S_w1f[cur][f][b], Bt, acc);
        #pragma unroll
        for(int r=0;r<4;r++)
            #pragma unroll
            for(int j=0;j<8;j++){
                const int row = th*32+ty*4+r, col = tx+j*32;
                float g = 2.f*(Ks[(ty*4+r)*SA + col] + acc[r][j] - SC_v[b][row*DD+col]);
                Gs[(ty*4+r)*SA + col] = g;
                SC_g[f][b][row*DD+col] = g;
            }
        gemm32<0>(Gs, S_w1f[cur][f][b], Bt, acc);
        #pragma unroll
        for(int r=0;r<4;r++)
            #pragma unroll
            for(int j=0;j<8;j++){
                const int row = th*32+ty*4+r, col = tx+j*32;
                SC_pre[s][b][row*DD+col] = acc[r][j]*dgeluf(zreg[r][j]);
            }
    } else if(bx < 96){
        // small-state (eta,alpha) per-token update pieces
        float* Ks = smem_;
        float* Bt = smem_ + TILE32;
        const int i = bx-64, th = i&1, t2 = i>>1, si = t2&1, b = t2>>1;
        const int s = 3+si;

        load_tile32(Ks, SC_k[b] + th*32*DD);
        __syncthreads();

        float acc[4][8];
        gemm32<1>(Ks, S_w2[cur][s][b], Bt, acc);
        const float* wsk = S_wsk[cur][si][b];
        const float* w1v = S_w1v[cur][si][b];
        #pragma unroll
        for(int r=0;r<4;r++){
            const int row = th*32+ty*4+r;
            float hreg[8]; float p = 0.f;
            #pragma unroll
            for(int j=0;j<8;j++){
                const int col = tx+j*32;
                float h = geluf(acc[r][j]);
                hreg[j] = h;
                SC_h2[s][b][row*DD+col] = h;
                p += Ks[(ty*4+r)*SA + col]*wsk[col] + h*w1v[col];
            }
            p = warp_sum(p);
            float g = 2.f*(256.f*p - SC_vsum[b][row]);
            if(tx==0) SC_gs[si][b][row] = g;
            #pragma unroll
            for(int j=0;j<8;j++){
                const int col = tx+j*32;
                SC_pre[s][b][row*DD+col] = g * w1v[col] * dgeluf(acc[r][j]);
            }
        }
    } else {
        // o = mem_fwd(q, mem-state) -> d_out ; also abar
        float* Qs = smem_;
        float* Hs = smem_ + TILE32;
        float* Bt = smem_ + 2*TILE32;
        const int i = bx-96, th = i&1, b = i>>1;

        load_tile32(Qs, SC_q[b] + th*32*DD);
        __syncthreads();

        float acc[4][8];
        gemm32<1>(Qs, S_w2[cur][5][b], Bt, acc);
        #pragma unroll
        for(int r=0;r<4;r++)
            #pragma unroll
            for(int j=0;j<8;j++)
                Hs[(ty*4+r)*SA + tx + j*32] = geluf(acc[r][j]);
        gemm32<1>(Hs, S_w1f[cur][3][b], Bt, acc);
        #pragma unroll
        for(int r=0;r<4;r++)
            #pragma unroll
            for(int j=0;j<8;j++){
                size_t off = ((size_t)b*TLEN + (size_t)chunk*CHK + th*32 + ty*4 + r)*DD + tx + j*32;
                dout[off] = Qs[(ty*4+r)*SA + tx + j*32] + acc[r][j];
            }
        if(th==0 && tid==0){
            float p = 1.f;
            #pragma unroll
            for(int t=0;t<CHK;t++) p *= SC_alpha[b][t];
            SC_abar[b] = p;
        }
    }
}

// ---------------- K3: weight updates  (grid 336) ----------------
// out[row,col] tile (64 x 256) = abar*Wold - sum_t (A[t,row]*eta[t]) * B[t,col]
__device__ __forceinline__ void k3_gemm(const float* __restrict__ Asrc, const float* __restrict__ Bsrc,
                                        const float* __restrict__ eta, float* Ges, float* Bs,
                                        int ot, float abar,
                                        const float* __restrict__ Wold, float* __restrict__ Wnew){
    const int tid = threadIdx.x, ty = tid>>5, tx = tid&31;
    #pragma unroll
    for(int l=0;l<16;l++){
        int idx = tid + l*256; int r = idx>>6, qc = (idx&63)<<2;
        *reinterpret_cast<float4*>(Bs + r*SA + qc) =
            *reinterpret_cast<const float4*>(Bsrc + r*DD + qc);
    }
    #pragma unroll
    for(int l=0;l<16;l++){
        int idx = tid + l*256; int t = idx>>6, o = idx&63;
        Ges[t*65 + o] = Asrc[t*DD + ot*64 + o] * eta[t];
    }
    __syncthreads();

    float acc[8][8];
    #pragma unroll
    for(int a=0;a<8;a++)
        #pragma unroll
        for(int j=0;j<8;j++) acc[a][j]=0.f;

    #pragma unroll 4
    for(int t=0;t<64;t++){
        float av[8];
        #pragma unroll
        for(int a=0;a<8;a++) av[a] = Ges[t*65 + ty*8 + a];
        #pragma unroll
        for(int j=0;j<8;j++){
            float bv = Bs[t*SA + tx + j*32];
            #pragma unroll
            for(int a=0;a<8;a++) acc[a][j] = fmaf(av[a], bv, acc[a][j]);
        }
    }
    #pragma unroll
    for(int a=0;a<8;a++){
        const int row = ot*64 + ty*8 + a;
        #pragma unroll
        for(int j=0;j<8;j++){
            const int col = tx + j*32;
            Wnew[row*DD+col] = abar*Wold[row*DD+col] - acc[a][j];
        }
    }
}

__global__ void __launch_bounds__(256) k3_weights(int chunk){
    extern __shared__ float smem_[];
    float* Ges = smem_;            // 64*65
    float* Bs  = smem_ + 4160;     // 64*SA
    const int bx = blockIdx.x;
    const int cur = chunk&1, nxt = cur^1;

    if(bx < 256){
        const int b = bx>>5, r = bx&31, f = r>>3, r2 = r&7, m = r2>>2, ot = r2&3;
        const int s = (f==3)? 5 : f;
        const float abar = SC_abar[b];
        if(m==0)
            k3_gemm(SC_g[f][b],  SC_h2[s][b], SC_eta[b], Ges, Bs, ot, abar,
                    S_w1f[cur][f][b], S_w1f[nxt][f][b]);
        else
            k3_gemm(SC_pre[s][b], SC_k[b],    SC_eta[b], Ges, Bs, ot, abar,
                    S_w2[cur][s][b],  S_w2[nxt][s][b]);
    } else {
        const int i = bx-256, b = i/10, rr = i%10, si = rr/5, qq = rr%5;
        const int s = 3+si;
        const float abar = SC_abar[b];
        if(qq < 4){
            k3_gemm(SC_pre[s][b], SC_k[b], SC_eta[b], Ges, Bs, qq, abar,
                    S_w2[cur][s][b], S_w2[nxt][s][b]);
        } else {
            const int j = threadIdx.x;   // 0..255
            float aA = 0.f, aB = 0.f;
            #pragma unroll 4
            for(int t=0;t<64;t++){
                float ge = SC_gs[si][b][t]*SC_eta[b][t];
                aA += ge * SC_h2[s][b][t*DD + j];
                aB += ge * SC_k[b][t*DD + j];
            }
            S_w1v[nxt][si][b][j] = abar*S_w1v[cur][si][b][j] - aA;
            S_wsk[nxt][si][b][j] = abar*S_wsk[cur][si][b][j] - aB;
        }
    }
}

// ---------------- launch ----------------
#define SMEM1 ((2*TILE32 + BTSZ)*4)          // 100352 B
#define SMEM2 ((3*TILE32 + BTSZ)*4)          // 133632 B
#define SMEM3 ((4160 + 64*SA)*4)             //  83200 B

extern "C" void kernel_launch(void* const* d_in, const int* in_sizes, int n_in,
                              void* d_out, int out_size){
    (void)in_sizes; (void)n_in; (void)out_size;
    const float* x   = (const float*)d_in[0];
    const float* k1w = (const float*)d_in[1];
    const float* k2w = (const float*)d_in[2];
    const float* v1w = (const float*)d_in[3];
    const float* v2w = (const float*)d_in[4];
    const float* q1w = (const float*)d_in[5];
    const float* q2w = (const float*)d_in[6];
    const float* e1w = (const float*)d_in[7];
    const float* e2w = (const float*)d_in[8];
    const float* esw = (const float*)d_in[9];
    const float* a1w = (const float*)d_in[10];
    const float* a2w = (const float*)d_in[11];
    const float* asw = (const float*)d_in[12];
    const float* m1w = (const float*)d_in[13];
    const float* m2w = (const float*)d_in[14];
    float* out = (float*)d_out;

    cudaFuncSetAttribute(k1_forward, cudaFuncAttributeMaxDynamicSharedMemorySize, SMEM1);
    cudaFuncSetAttribute(k2_token,   cudaFuncAttributeMaxDynamicSharedMemorySize, SMEM2);
    cudaFuncSetAttribute(k3_weights, cudaFuncAttributeMaxDynamicSharedMemorySize, SMEM3);

    k0_init<<<dim3(DD*DD/256, 11), 256>>>(k1w,k2w,v1w,v2w,q1w,q2w,e1w,e2w,esw,a1w,a2w,asw,m1w,m2w);

    for(int c=0;c<NC;c++){
        k1_forward<<<80, 256, SMEM1>>>(x, c);
        k2_token  <<<112,256, SMEM2>>>(out, c);
        k3_weights<<<336,256, SMEM3>>>(c);
    }
}

// round 3
// speedup vs baseline: 1.6886x; 1.6886x over previous
#include <cuda_runtime.h>
#include <math.h>

typedef unsigned long long u64;

#define DD   256
#define BB   8
#define CHK  64
#define NC   64
#define TLEN 4096

#define SA    260               // activation tile row stride (floats)
#define STB   34                // B^T staging stride (k-pack, conflict-free LDS.64)
#define SNB   260               // normal-orientation staging stride (col-pack)
#define XTILE (16*SA)           // 4160 floats per 16x256 tile
#define BTBUF (256*STB)         // 8704 floats (>= 32*SNB = 8320)

// ---------------- persistent state (double-buffered) ----------------
// states: 0=k 1=v 2=q 3=eta 4=alpha 5=mem ; full-w1 index: k,v,q,mem -> 0,1,2,3
static __device__ float S_w1f[2][4][BB][DD*DD];
static __device__ float S_w2 [2][6][BB][DD*DD];
static __device__ float S_w1v[2][2][BB][DD];
static __device__ float S_wsk[2][2][BB][DD];

// ---------------- per-chunk scratch ----------------
static __device__ float SC_k [BB][CHK*DD];
static __device__ float SC_v [BB][CHK*DD];
static __device__ float SC_q [BB][CHK*DD];
static __device__ float SC_h2[6][BB][CHK*DD];
static __device__ float SC_g [4][BB][CHK*DD];
static __device__ float SC_pre[6][BB][CHK*DD];
static __device__ float SC_eta[BB][CHK];
static __device__ float SC_alpha[BB][CHK];
static __device__ float SC_vsum[BB][CHK];
static __device__ float SC_gs[2][BB][CHK];
static __device__ float SC_abar[BB];

// ---------------- helpers ----------------
__device__ __forceinline__ void fmaX2(u64 &d, u64 a, u64 b){
    asm("fma.rn.f32x2 %0, %1, %2, %0;" : "+l"(d) : "l"(a), "l"(b));
}
__device__ __forceinline__ u64 pk2(float lo, float hi){
    u64 r; asm("mov.b64 %0, {%1, %2};" : "=l"(r) : "f"(lo), "f"(hi)); return r;
}
__device__ __forceinline__ float2 up2(u64 v){
    float lo, hi; asm("mov.b64 {%0, %1}, %2;" : "=f"(lo), "=f"(hi) : "l"(v));
    return make_float2(lo, hi);
}
__device__ __forceinline__ float red2(u64 v){ float2 t = up2(v); return t.x + t.y; }

__device__ __forceinline__ float geluf(float z){
    return 0.5f*z*(1.0f + erff(z*0.70710678118654752f));
}
__device__ __forceinline__ float dgeluf(float z){
    float cdf = 0.5f*(1.0f + erff(z*0.70710678118654752f));
    float pdf = expf(-0.5f*z*z)*0.39894228040143267f;
    return cdf + z*pdf;
}
__device__ __forceinline__ float warp_sum(float v){
    #pragma unroll
    for(int o=16;o>0;o>>=1) v += __shfl_xor_sync(0xffffffffu, v, o);
    return v;
}

// load 16x256 global (row stride 256) -> smem tile (row stride SA), 128 threads
__device__ __forceinline__ void load_tile16(float* dst, const float* __restrict__ src){
    const int tid = threadIdx.x;
    #pragma unroll
    for(int l=0;l<8;l++){
        int idx = tid + l*128;            // 1024 float4s
        int r = idx>>6, qc = (idx&63)<<2;
        *reinterpret_cast<float4*>(dst + r*SA + qc) =
            *reinterpret_cast<const float4*>(src + r*DD + qc);
    }
}

// ---------------- TB GEMM, k-packed f32x2 ----------------
// OUT[t,j] = sum_c A[t,c]*B[j,c]; A: smem 16xDD (stride SA); B: global DDxDD.
// 128 threads: warp wid owns rows wid*4..+3; lane tx owns cols tx+32*jj.
// acc[r][j] holds (even-c partial, odd-c partial); reduce with red2().
__device__ __forceinline__ void gemmTB(const float* As, const float* __restrict__ Bg,
                                       float* Bt, u64 (&acc)[4][8]){
    const int tid = threadIdx.x, wid = tid>>5, tx = tid&31;
    #pragma unroll
    for(int r=0;r<4;r++)
        #pragma unroll
        for(int j=0;j<8;j++) acc[r][j] = 0ull;

    for(int c0=0;c0<DD;c0+=32){
        // stage B[j][c0..c0+31] -> Bt[j*STB + cc]
        #pragma unroll
        for(int l=0;l<16;l++){
            int idx = tid + l*128;               // 2048 float4s
            int j = idx>>3, qc = (idx&7)<<2;
            float4 v = *reinterpret_cast<const float4*>(Bg + j*DD + c0 + qc);
            float2* p = reinterpret_cast<float2*>(Bt + j*STB + qc);
            p[0] = make_float2(v.x, v.y);
            p[1] = make_float2(v.z, v.w);
        }
        __syncthreads();
        const float* Arow = As + wid*4*SA + c0;
        #pragma unroll
        for(int c2=0;c2<16;c2++){
            u64 a0 = *reinterpret_cast<const u64*>(Arow + 0*SA + 2*c2);
            u64 a1 = *reinterpret_cast<const u64*>(Arow + 1*SA + 2*c2);
            u64 a2 = *reinterpret_cast<const u64*>(Arow + 2*SA + 2*c2);
            u64 a3 = *reinterpret_cast<const u64*>(Arow + 3*SA + 2*c2);
            #pragma unroll
            for(int j=0;j<8;j++){
                u64 b = *reinterpret_cast<const u64*>(Bt + (tx+32*j)*STB + 2*c2);
                fmaX2(acc[0][j], a0, b);
                fmaX2(acc[1][j], a1, b);
                fmaX2(acc[2][j], a2, b);
                fmaX2(acc[3][j], a3, b);
            }
        }
        __syncthreads();
    }
}

// ---------------- normal GEMM, col-packed f32x2 ----------------
// OUT[t,j] = sum_c A[t,c]*B[c,j]; lane tx owns col pairs (2tx+64p, +1), p=0..3.
__device__ __forceinline__ void gemmN(const float* As, const float* __restrict__ Bg,
                                      float* Bt, u64 (&acc)[4][4]){
    const int tid = threadIdx.x, wid = tid>>5, tx = tid&31;
    #pragma unroll
    for(int r=0;r<4;r++)
        #pragma unroll
        for(int p=0;p<4;p++) acc[r][p] = 0ull;

    for(int c0=0;c0<DD;c0+=32){
        #pragma unroll
        for(int l=0;l<16;l++){
            int idx = tid + l*128;
            int cc = idx>>6, qc = (idx&63)<<2;
            *reinterpret_cast<float4*>(Bt + cc*SNB + qc) =
                *reinterpret_cast<const float4*>(Bg + (c0+cc)*DD + qc);
        }
        __syncthreads();
        const float* Arow = As + wid*4*SA + c0;
        #pragma unroll
        for(int cc=0;cc<32;cc++){
            u64 a0 = pk2(Arow[0*SA+cc], Arow[0*SA+cc]);
            u64 a1 = pk2(Arow[1*SA+cc], Arow[1*SA+cc]);
            u64 a2 = pk2(Arow[2*SA+cc], Arow[2*SA+cc]);
            u64 a3 = pk2(Arow[3*SA+cc], Arow[3*SA+cc]);
            #pragma unroll
            for(int p=0;p<4;p++){
                u64 b = *reinterpret_cast<const u64*>(Bt + cc*SNB + 2*tx + 64*p);
                fmaX2(acc[0][p], a0, b);
                fmaX2(acc[1][p], a1, b);
                fmaX2(acc[2][p], a2, b);
                fmaX2(acc[3][p], a3, b);
            }
        }
        __syncthreads();
    }
}

// ---------------- K0: initialize per-batch state ----------------
__global__ void k0_init(const float* __restrict__ k1w, const float* __restrict__ k2w,
                        const float* __restrict__ v1w, const float* __restrict__ v2w,
                        const float* __restrict__ q1w, const float* __restrict__ q2w,
                        const float* __restrict__ e1w, const float* __restrict__ e2w,
                        const float* __restrict__ esw, const float* __restrict__ a1w,
                        const float* __restrict__ a2w, const float* __restrict__ asw,
                        const float* __restrict__ m1w, const float* __restrict__ m2w){
    const int gid = blockIdx.x*blockDim.x + threadIdx.x;
    const int m = blockIdx.y;
    if(m<4){
        const float* src = (m==0)?k1w:(m==1)?v1w:(m==2)?q1w:m1w;
        float v = src[gid];
        #pragma unroll
        for(int b=0;b<BB;b++) S_w1f[0][m][b][gid] = v;
    } else if(m<10){
        const int s = m-4;
        const float* src = (s==0)?k2w:(s==1)?v2w:(s==2)?q2w:(s==3)?e2w:(s==4)?a2w:m2w;
        float v = src[gid];
        #pragma unroll
        for(int b=0;b<BB;b++) S_w2[0][s][b][gid] = v;
    } else {
        if(gid < DD){
            #pragma unroll
            for(int b=0;b<BB;b++){
                S_w1v[0][0][b][gid] = e1w[gid];
                S_w1v[0][1][b][gid] = a1w[gid];
                S_wsk[0][0][b][gid] = esw[gid];
                S_wsk[0][1][b][gid] = asw[gid];
            }
        }
    }
}

// ---------------- K1: forwards k,v,q,eta,alpha (grid 160 x 128thr) ----------------
__global__ void __launch_bounds__(128) k1_forward(const float* __restrict__ x, int chunk){
    extern __shared__ float sm[];
    float* Xs = sm;
    float* Hs = sm + XTILE;
    float* Bt = sm + 2*XTILE;
    const int tid = threadIdx.x, wid = tid>>5, tx = tid&31;
    const int bx = blockIdx.x;
    const int th = bx&3, q2 = bx>>2, s = q2%5, b = q2/5;
    const int cur = chunk&1;
    const int tok0 = chunk*CHK + th*16;

    load_tile16(Xs, x + ((size_t)b*TLEN + tok0)*DD);
    __syncthreads();

    u64 acc[4][8];
    gemmTB(Xs, S_w2[cur][s][b], Bt, acc);

    if(s<3){
        #pragma unroll
        for(int r=0;r<4;r++)
            #pragma unroll
            for(int j=0;j<8;j++)
                Hs[(wid*4+r)*SA + tx + 32*j] = geluf(red2(acc[r][j]));
        gemmTB(Hs, S_w1f[cur][s][b], Bt, acc);
        #pragma unroll
        for(int r=0;r<4;r++){
            const int row = th*16 + wid*4 + r;
            float out[8]; float ss = 0.f, vs = 0.f;
            #pragma unroll
            for(int j=0;j<8;j++){
                const int col = tx + 32*j;
                float o = Xs[(wid*4+r)*SA + col] + red2(acc[r][j]);
                out[j] = o; ss += o*o; vs += o;
            }
            if(s==1){
                vs = warp_sum(vs);
                #pragma unroll
                for(int j=0;j<8;j++) SC_v[b][row*DD + tx + 32*j] = out[j];
                if(tx==0) SC_vsum[b][row] = vs;
            } else {
                ss = warp_sum(ss);
                float inv = 1.f / fmaxf(sqrtf(ss), 1e-6f);
                float* dst = (s==0)? SC_k[b] : SC_q[b];
                #pragma unroll
                for(int j=0;j<8;j++) dst[row*DD + tx + 32*j] = out[j]*inv;
            }
        }
    } else {
        const int si = s-3;
        const float* wsk = S_wsk[cur][si][b];
        const float* w1v = S_w1v[cur][si][b];
        float wk[8], wv[8];
        #pragma unroll
        for(int j=0;j<8;j++){ wk[j] = wsk[tx+32*j]; wv[j] = w1v[tx+32*j]; }
        #pragma unroll
        for(int r=0;r<4;r++){
            const int row = th*16 + wid*4 + r;
            float p = 0.f;
            #pragma unroll
            for(int j=0;j<8;j++){
                float h = geluf(red2(acc[r][j]));
                p += Xs[(wid*4+r)*SA + tx + 32*j]*wk[j] + h*wv[j];
            }
            p = warp_sum(p);
            if(tx==0){
                if(si==0){ float sp = (p>20.f)? p : log1pf(expf(p)); SC_eta[b][row] = sp*0.001f; }
                else       SC_alpha[b][row] = 1.f/(1.f+expf(-p));
            }
        }
    }
}

// ---------------- K2: per-token update terms + output (grid 224 x 128thr) ----------------
__global__ void __launch_bounds__(128) k2_token(float* __restrict__ dout, int chunk){
    extern __shared__ float sm[];
    const int tid = threadIdx.x, wid = tid>>5, tx = tid&31;
    const int bx = blockIdx.x, cur = chunk&1;

    if(bx < 128){
        float* Ks = sm;
        float* Hs = sm + XTILE;
        float* Gs = sm + 2*XTILE;
        float* Bt = sm + 3*XTILE;
        const int th = bx&3, f = (bx>>2)&3, b = bx>>4;
        const int s = (f==3)? 5 : f;

        load_tile16(Ks, SC_k[b] + th*16*DD);
        __syncthreads();

        u64 acc[4][8]; float zreg[4][8];
        gemmTB(Ks, S_w2[cur][s][b], Bt, acc);
        #pragma unroll
        for(int r=0;r<4;r++)
            #pragma unroll
            for(int j=0;j<8;j++){
                float z = red2(acc[r][j]); zreg[r][j] = z;
                float h = geluf(z);
                Hs[(wid*4+r)*SA + tx + 32*j] = h;
                SC_h2[s][b][(th*16 + wid*4 + r)*DD + tx + 32*j] = h;
            }
        gemmTB(Hs, S_w1f[cur][f][b], Bt, acc);
        #pragma unroll
        for(int r=0;r<4;r++)
            #pragma unroll
            for(int j=0;j<8;j++){
                const int row = th*16 + wid*4 + r, col = tx + 32*j;
                float g = 2.f*(Ks[(wid*4+r)*SA + col] + red2(acc[r][j]) - SC_v[b][row*DD+col]);
                Gs[(wid*4+r)*SA + col] = g;
                SC_g[f][b][row*DD+col] = g;
                Ks[(wid*4+r)*SA + col] = dgeluf(zreg[r][j]);  // repurpose Ks as dgelu tile
            }
        u64 accN[4][4];
        gemmN(Gs, S_w1f[cur][f][b], Bt, accN);
        #pragma unroll
        for(int r=0;r<4;r++){
            const int row = th*16 + wid*4 + r;
            #pragma unroll
            for(int p=0;p<4;p++){
                float2 v = up2(accN[r][p]);
                const int c0 = 2*tx + 64*p;
                SC_pre[s][b][row*DD + c0]     = v.x * Ks[(wid*4+r)*SA + c0];
                SC_pre[s][b][row*DD + c0 + 1] = v.y * Ks[(wid*4+r)*SA + c0 + 1];
            }
        }
    } else if(bx < 192){
        float* Ks = sm;
        float* Bt = sm + XTILE;
        const int i = bx-128, th = i&3, si = (i>>2)&1, b = i>>3;
        const int s = 3+si;

        load_tile16(Ks, SC_k[b] + th*16*DD);
        __syncthreads();

        u64 acc[4][8];
        gemmTB(Ks, S_w2[cur][s][b], Bt, acc);
        const float* wsk = S_wsk[cur][si][b];
        const float* w1v = S_w1v[cur][si][b];
        float wk[8], wv[8];
        #pragma unroll
        for(int j=0;j<8;j++){ wk[j] = wsk[tx+32*j]; wv[j] = w1v[tx+32*j]; }
        #pragma unroll
        for(int r=0;r<4;r++){
            const int row = th*16 + wid*4 + r;
            float hr[8], zr[8]; float p = 0.f;
            #pragma unroll
            for(int j=0;j<8;j++){
                float z = red2(acc[r][j]); zr[j] = z;
                float h = geluf(z); hr[j] = h;
                SC_h2[s][b][row*DD + tx + 32*j] = h;
                p += Ks[(wid*4+r)*SA + tx + 32*j]*wk[j] + h*wv[j];
            }
            p = warp_sum(p);
            float g = 2.f*(256.f*p - SC_vsum[b][row]);
            if(tx==0) SC_gs[si][b][row] = g;
            #pragma unroll
            for(int j=0;j<8;j++)
                SC_pre[s][b][row*DD + tx + 32*j] = g * wv[j] * dgeluf(zr[j]);
        }
    } else {
        float* Qs = sm;
        float* Hs = sm + XTILE;
        float* Bt = sm + 2*XTILE;
        const int i = bx-192, th = i&3, b = i>>2;

        load_tile16(Qs, SC_q[b] + th*16*DD);
        __syncthreads();

        u64 acc[4][8];
        gemmTB(Qs, S_w2[cur][5][b], Bt, acc);
        #pragma unroll
        for(int r=0;r<4;r++)
            #pragma unroll
            for(int j=0;j<8;j++)
                Hs[(wid*4+r)*SA + tx + 32*j] = geluf(red2(acc[r][j]));
        gemmTB(Hs, S_w1f[cur][3][b], Bt, acc);
        #pragma unroll
        for(int r=0;r<4;r++)
            #pragma unroll
            for(int j=0;j<8;j++){
                size_t off = ((size_t)b*TLEN + (size_t)chunk*CHK + th*16 + wid*4 + r)*DD + tx + 32*j;
                dout[off] = Qs[(wid*4+r)*SA + tx + 32*j] + red2(acc[r][j]);
            }
        if(th==0 && tid==0){
            float p = 1.f;
            #pragma unroll
            for(int t=0;t<CHK;t++) p *= SC_alpha[b][t];
            SC_abar[b] = p;
        }
    }
}

// ---------------- K3: weight updates (grid 656 x 256thr) ----------------
// Tile: 64 out-rows x 128 cols, K=64, rows-packed f32x2.
__global__ void __launch_bounds__(256) k3_weights(int chunk){
    extern __shared__ float sm[];
    float* Ges = sm;            // 64 x 66
    float* Bs  = sm + 64*66;    // 64 x 132
    const int tid = threadIdx.x, wid = tid>>5, tx = tid&31;
    const int bx = blockIdx.x;
    const int cur = chunk&1, nxt = cur^1;

    if(bx < 640){
        int b, ot, ch;
        const float *A, *Bsrc, *Wold; float* Wnew;
        if(bx < 512){
            b = bx>>6; int r = bx&63;
            int f = r>>4, m = (r>>3)&1; ot = (r>>1)&3; ch = r&1;
            int s = (f==3)? 5 : f;
            if(m==0){ A = SC_g[f][b];   Bsrc = SC_h2[s][b]; Wold = S_w1f[cur][f][b]; Wnew = S_w1f[nxt][f][b]; }
            else    { A = SC_pre[s][b]; Bsrc = SC_k[b];     Wold = S_w2[cur][s][b];  Wnew = S_w2[nxt][s][b]; }
        } else {
            int i = bx-512; b = i>>4; int r = i&15;
            int si = r>>3; ot = (r>>1)&3; ch = r&1;
            int s = 3+si;
            A = SC_pre[s][b]; Bsrc = SC_k[b]; Wold = S_w2[cur][s][b]; Wnew = S_w2[nxt][s][b];
        }
        const float abar = SC_abar[b];
        const float* eta = SC_eta[b];

        // stage B cols [ch*128, +128)
        #pragma unroll
        for(int l=0;l<8;l++){
            int idx = tid + l*256;           // 2048 float4s
            int t = idx>>5, qc = (idx&31)<<2;
            *reinterpret_cast<float4*>(Bs + t*132 + qc) =
                *reinterpret_cast<const float4*>(Bsrc + t*DD + ch*128 + qc);
        }
        // stage Ges[t][o] = A[t, ot*64+o] * eta[t]
        #pragma unroll
        for(int l=0;l<4;l++){
            int idx = tid + l*256;           // 1024 float4s
            int t = idx>>4, oq = (idx&15)<<2;
            float e = eta[t];
            float4 v = *reinterpret_cast<const float4*>(A + t*DD + ot*64 + oq);
            float2* p = reinterpret_cast<float2*>(Ges + t*66 + oq);
            p[0] = make_float2(v.x*e, v.y*e);
            p[1] = make_float2(v.z*e, v.w*e);
        }
        __syncthreads();

        u64 acc[4][4];
        #pragma unroll
        for(int rp=0;rp<4;rp++)
            #pragma unroll
            for(int j=0;j<4;j++) acc[rp][j] = 0ull;

        #pragma unroll 4
        for(int t=0;t<64;t++){
            u64 a[4];
            #pragma unroll
            for(int rp=0;rp<4;rp++)
                a[rp] = *reinterpret_cast<const u64*>(Ges + t*66 + wid*8 + 2*rp);
            float4 bv = *reinterpret_cast<const float4*>(Bs + t*132 + tx*4);
            u64 b0 = pk2(bv.x,bv.x), b1 = pk2(bv.y,bv.y), b2 = pk2(bv.z,bv.z), b3 = pk2(bv.w,bv.w);
            #pragma unroll
            for(int rp=0;rp<4;rp++){
                fmaX2(acc[rp][0], a[rp], b0);
                fmaX2(acc[rp][1], a[rp], b1);
                fmaX2(acc[rp][2], a[rp], b2);
                fmaX2(acc[rp][3], a[rp], b3);
            }
        }
        #pragma unroll
        for(int rp=0;rp<4;rp++){
            const int row0 = ot*64 + wid*8 + 2*rp;
            size_t off0 = (size_t)row0*DD + ch*128 + tx*4;
            float4 w0 = *reinterpret_cast<const float4*>(Wold + off0);
            float4 w1 = *reinterpret_cast<const float4*>(Wold + off0 + DD);
            float2 c0 = up2(acc[rp][0]), c1 = up2(acc[rp][1]);
            float2 c2 = up2(acc[rp][2]), c3 = up2(acc[rp][3]);
            float4 o0 = make_float4(abar*w0.x - c0.x, abar*w0.y - c1.x,
                                    abar*w0.z - c2.x, abar*w0.w - c3.x);
            float4 o1 = make_float4(abar*w1.x - c0.y, abar*w1.y - c1.y,
                                    abar*w1.z - c2.y, abar*w1.w - c3.y);
            *reinterpret_cast<float4*>(Wnew + off0)      = o0;
            *reinterpret_cast<float4*>(Wnew + off0 + DD) = o1;
        }
    } else {
        const int i = bx-640, b = i>>1, si = i&1, s = 3+si;
        const float abar = SC_abar[b];
        const int j = tid;
        float aA = 0.f, aB = 0.f;
        #pragma unroll 4
        for(int t=0;t<CHK;t++){
            float ge = SC_gs[si][b][t]*SC_eta[b][t];
            aA += ge * SC_h2[s][b][t*DD + j];
            aB += ge * SC_k[b][t*DD + j];
        }
        S_w1v[nxt][si][b][j] = abar*S_w1v[cur][si][b][j] - aA;
        S_wsk[nxt][si][b][j] = abar*S_wsk[cur][si][b][j] - aB;
    }
}

// ---------------- launch ----------------
#define SMEM1 ((2*XTILE + BTBUF)*4)      // 68096 B
#define SMEM2 ((3*XTILE + BTBUF)*4)      // 84736 B
#define SMEM3 ((64*66 + 64*132)*4)       // 50688 B

extern "C" void kernel_launch(void* const* d_in, const int* in_sizes, int n_in,
                              void* d_out, int out_size){
    (void)in_sizes; (void)n_in; (void)out_size;
    const float* x   = (const float*)d_in[0];
    const float* k1w = (const float*)d_in[1];
    const float* k2w = (const float*)d_in[2];
    const float* v1w = (const float*)d_in[3];
    const float* v2w = (const float*)d_in[4];
    const float* q1w = (const float*)d_in[5];
    const float* q2w = (const float*)d_in[6];
    const float* e1w = (const float*)d_in[7];
    const float* e2w = (const float*)d_in[8];
    const float* esw = (const float*)d_in[9];
    const float* a1w = (const float*)d_in[10];
    const float* a2w = (const float*)d_in[11];
    const float* asw = (const float*)d_in[12];
    const float* m1w = (const float*)d_in[13];
    const float* m2w = (const float*)d_in[14];
    float* out = (float*)d_out;

    cudaFuncSetAttribute(k1_forward, cudaFuncAttributeMaxDynamicSharedMemorySize, SMEM1);
    cudaFuncSetAttribute(k2_token,   cudaFuncAttributeMaxDynamicSharedMemorySize, SMEM2);
    cudaFuncSetAttribute(k3_weights, cudaFuncAttributeMaxDynamicSharedMemorySize, SMEM3);

    k0_init<<<dim3(DD*DD/256, 11), 256>>>(k1w,k2w,v1w,v2w,q1w,q2w,e1w,e2w,esw,a1w,a2w,asw,m1w,m2w);

    for(int c=0;c<NC;c++){
        k1_forward<<<160, 128, SMEM1>>>(x, c);
        k2_token  <<<224, 128, SMEM2>>>(out, c);
        k3_weights<<<656, 256, SMEM3>>>(c);
    }
}

// round 4
// speedup vs baseline: 1.6973x; 1.0052x over previous
#include <cuda_runtime.h>
#include <math.h>

typedef unsigned long long u64;

#define DD   256
#define BB   8
#define CHK  64
#define NC   64
#define TLEN 4096

#define SA    260               // activation tile row stride (floats)
#define STB   34                // B^T staging stride (k-pack, conflict-free LDS.64)
#define SNB   260               // normal-orientation staging stride (col-pack)
#define XTILE (16*SA)           // 4160 floats per 16x256 tile
#define BTBUF (256*STB)         // 8704 floats (>= 32*SNB = 8320)

// ---------------- persistent state (double-buffered) ----------------
// states: 0=k 1=v 2=q 3=eta 4=alpha 5=mem ; full-w1 index: k,v,q,mem -> 0,1,2,3
static __device__ float S_w1f[2][4][BB][DD*DD];
static __device__ float S_w2 [2][6][BB][DD*DD];
static __device__ float S_w1v[2][2][BB][DD];
static __device__ float S_wsk[2][2][BB][DD];

// ---------------- per-chunk scratch ----------------
static __device__ float SC_k [BB][CHK*DD];
static __device__ float SC_v [BB][CHK*DD];
static __device__ float SC_q [BB][CHK*DD];
static __device__ float SC_h2[6][BB][CHK*DD];
static __device__ float SC_g [4][BB][CHK*DD];
static __device__ float SC_pre[6][BB][CHK*DD];
static __device__ float SC_eta[BB][CHK];
static __device__ float SC_alpha[BB][CHK];
static __device__ float SC_vsum[BB][CHK];
static __device__ float SC_gs[2][BB][CHK];
static __device__ float SC_abar[BB];

// ---------------- helpers ----------------
__device__ __forceinline__ void fmaX2(u64 &d, u64 a, u64 b){
    asm("fma.rn.f32x2 %0, %1, %2, %0;" : "+l"(d) : "l"(a), "l"(b));
}
__device__ __forceinline__ u64 pk2(float lo, float hi){
    u64 r; asm("mov.b64 %0, {%1, %2};" : "=l"(r) : "f"(lo), "f"(hi)); return r;
}
__device__ __forceinline__ float2 up2(u64 v){
    float lo, hi; asm("mov.b64 {%0, %1}, %2;" : "=f"(lo), "=f"(hi) : "l"(v));
    return make_float2(lo, hi);
}
__device__ __forceinline__ float red2(u64 v){ float2 t = up2(v); return t.x + t.y; }

__device__ __forceinline__ float geluf(float z){
    return 0.5f*z*(1.0f + erff(z*0.70710678118654752f));
}
__device__ __forceinline__ float dgeluf(float z){
    float cdf = 0.5f*(1.0f + erff(z*0.70710678118654752f));
    float pdf = expf(-0.5f*z*z)*0.39894228040143267f;
    return cdf + z*pdf;
}
__device__ __forceinline__ float warp_sum(float v){
    #pragma unroll
    for(int o=16;o>0;o>>=1) v += __shfl_xor_sync(0xffffffffu, v, o);
    return v;
}

// load 16x256 global (row stride 256) -> smem tile (row stride SA), 128 threads
__device__ __forceinline__ void load_tile16(float* dst, const float* __restrict__ src){
    const int tid = threadIdx.x;
    #pragma unroll
    for(int l=0;l<8;l++){
        int idx = tid + l*128;            // 1024 float4s
        int r = idx>>6, qc = (idx&63)<<2;
        *reinterpret_cast<float4*>(dst + r*SA + qc) =
            *reinterpret_cast<const float4*>(src + r*DD + qc);
    }
}

// ---------------- TB GEMM, k-packed f32x2 ----------------
// OUT[t,j] = sum_c A[t,c]*B[j,c]; A: smem 16xDD (stride SA); B: global DDxDD.
// 128 threads: warp wid owns rows wid*4..+3; lane tx owns cols tx+32*jj.
// acc[r][j] holds (even-c partial, odd-c partial); reduce with red2().
__device__ __forceinline__ void gemmTB(const float* As, const float* __restrict__ Bg,
                                       float* Bt, u64 (&acc)[4][8]){
    const int tid = threadIdx.x, wid = tid>>5, tx = tid&31;
    #pragma unroll
    for(int r=0;r<4;r++)
        #pragma unroll
        for(int j=0;j<8;j++) acc[r][j] = 0ull;

    for(int c0=0;c0<DD;c0+=32){
        // stage B[j][c0..c0+31] -> Bt[j*STB + cc]
        #pragma unroll
        for(int l=0;l<16;l++){
            int idx = tid + l*128;               // 2048 float4s
            int j = idx>>3, qc = (idx&7)<<2;
            float4 v = *reinterpret_cast<const float4*>(Bg + j*DD + c0 + qc);
            float2* p = reinterpret_cast<float2*>(Bt + j*STB + qc);
            p[0] = make_float2(v.x, v.y);
            p[1] = make_float2(v.z, v.w);
        }
        __syncthreads();
        const float* Arow = As + wid*4*SA + c0;
        #pragma unroll
        for(int c2=0;c2<16;c2++){
            u64 a0 = *reinterpret_cast<const u64*>(Arow + 0*SA + 2*c2);
            u64 a1 = *reinterpret_cast<const u64*>(Arow + 1*SA + 2*c2);
            u64 a2 = *reinterpret_cast<const u64*>(Arow + 2*SA + 2*c2);
            u64 a3 = *reinterpret_cast<const u64*>(Arow + 3*SA + 2*c2);
            #pragma unroll
            for(int j=0;j<8;j++){
                u64 b = *reinterpret_cast<const u64*>(Bt + (tx+32*j)*STB + 2*c2);
                fmaX2(acc[0][j], a0, b);
                fmaX2(acc[1][j], a1, b);
                fmaX2(acc[2][j], a2, b);
                fmaX2(acc[3][j], a3, b);
            }
        }
        __syncthreads();
    }
}

// ---------------- normal GEMM, col-packed f32x2 ----------------
// OUT[t,j] = sum_c A[t,c]*B[c,j]; lane tx owns col pairs (2tx+64p, +1), p=0..3.
__device__ __forceinline__ void gemmN(const float* As, const float* __restrict__ Bg,
                                      float* Bt, u64 (&acc)[4][4]){
    const int tid = threadIdx.x, wid = tid>>5, tx = tid&31;
    #pragma unroll
    for(int r=0;r<4;r++)
        #pragma unroll
        for(int p=0;p<4;p++) acc[r][p] = 0ull;

    for(int c0=0;c0<DD;c0+=32){
        #pragma unroll
        for(int l=0;l<16;l++){
            int idx = tid + l*128;
            int cc = idx>>6, qc = (idx&63)<<2;
            *reinterpret_cast<float4*>(Bt + cc*SNB + qc) =
                *reinterpret_cast<const float4*>(Bg + (c0+cc)*DD + qc);
        }
        __syncthreads();
        const float* Arow = As + wid*4*SA + c0;
        #pragma unroll
        for(int cc=0;cc<32;cc++){
            u64 a0 = pk2(Arow[0*SA+cc], Arow[0*SA+cc]);
            u64 a1 = pk2(Arow[1*SA+cc], Arow[1*SA+cc]);
            u64 a2 = pk2(Arow[2*SA+cc], Arow[2*SA+cc]);
            u64 a3 = pk2(Arow[3*SA+cc], Arow[3*SA+cc]);
            #pragma unroll
            for(int p=0;p<4;p++){
                u64 b = *reinterpret_cast<const u64*>(Bt + cc*SNB + 2*tx + 64*p);
                fmaX2(acc[0][p], a0, b);
                fmaX2(acc[1][p], a1, b);
                fmaX2(acc[2][p], a2, b);
                fmaX2(acc[3][p], a3, b);
            }
        }
        __syncthreads();
    }
}

// ---------------- K0: initialize per-batch state ----------------
__global__ void k0_init(const float* __restrict__ k1w, const float* __restrict__ k2w,
                        const float* __restrict__ v1w, const float* __restrict__ v2w,
                        const float* __restrict__ q1w, const float* __restrict__ q2w,
                        const float* __restrict__ e1w, const float* __restrict__ e2w,
                        const float* __restrict__ esw, const float* __restrict__ a1w,
                        const float* __restrict__ a2w, const float* __restrict__ asw,
                        const float* __restrict__ m1w, const float* __restrict__ m2w){
    const int gid = blockIdx.x*blockDim.x + threadIdx.x;
    const int m = blockIdx.y;
    if(m<4){
        const float* src = (m==0)?k1w:(m==1)?v1w:(m==2)?q1w:m1w;
        float v = src[gid];
        #pragma unroll
        for(int b=0;b<BB;b++) S_w1f[0][m][b][gid] = v;
    } else if(m<10){
        const int s = m-4;
        const float* src = (s==0)?k2w:(s==1)?v2w:(s==2)?q2w:(s==3)?e2w:(s==4)?a2w:m2w;
        float v = src[gid];
        #pragma unroll
        for(int b=0;b<BB;b++) S_w2[0][s][b][gid] = v;
    } else {
        if(gid < DD){
            #pragma unroll
            for(int b=0;b<BB;b++){
                S_w1v[0][0][b][gid] = e1w[gid];
                S_w1v[0][1][b][gid] = a1w[gid];
                S_wsk[0][0][b][gid] = esw[gid];
                S_wsk[0][1][b][gid] = asw[gid];
            }
        }
    }
}

// ---------------- K1: forwards k,v,q,eta,alpha (grid 160 x 128thr) ----------------
__global__ void __launch_bounds__(128) k1_forward(const float* __restrict__ x, int chunk){
    extern __shared__ float sm[];
    float* Xs = sm;
    float* Hs = sm + XTILE;
    float* Bt = sm + 2*XTILE;
    const int tid = threadIdx.x, wid = tid>>5, tx = tid&31;
    const int bx = blockIdx.x;
    const int th = bx&3, q2 = bx>>2, s = q2%5, b = q2/5;
    const int cur = chunk&1;
    const int tok0 = chunk*CHK + th*16;

    load_tile16(Xs, x + ((size_t)b*TLEN + tok0)*DD);
    __syncthreads();

    u64 acc[4][8];
    gemmTB(Xs, S_w2[cur][s][b], Bt, acc);

    if(s<3){
        #pragma unroll
        for(int r=0;r<4;r++)
            #pragma unroll
            for(int j=0;j<8;j++)
                Hs[(wid*4+r)*SA + tx + 32*j] = geluf(red2(acc[r][j]));
        gemmTB(Hs, S_w1f[cur][s][b], Bt, acc);
        #pragma unroll
        for(int r=0;r<4;r++){
            const int row = th*16 + wid*4 + r;
            float out[8]; float ss = 0.f, vs = 0.f;
            #pragma unroll
            for(int j=0;j<8;j++){
                const int col = tx + 32*j;
                float o = Xs[(wid*4+r)*SA + col] + red2(acc[r][j]);
                out[j] = o; ss += o*o; vs += o;
            }
            if(s==1){
                vs = warp_sum(vs);
                #pragma unroll
                for(int j=0;j<8;j++) SC_v[b][row*DD + tx + 32*j] = out[j];
                if(tx==0) SC_vsum[b][row] = vs;
            } else {
                ss = warp_sum(ss);
                float inv = 1.f / fmaxf(sqrtf(ss), 1e-6f);
                float* dst = (s==0)? SC_k[b] : SC_q[b];
                #pragma unroll
                for(int j=0;j<8;j++) dst[row*DD + tx + 32*j] = out[j]*inv;
            }
        }
    } else {
        const int si = s-3;
        const float* wsk = S_wsk[cur][si][b];
        const float* w1v = S_w1v[cur][si][b];
        float wk[8], wv[8];
        #pragma unroll
        for(int j=0;j<8;j++){ wk[j] = wsk[tx+32*j]; wv[j] = w1v[tx+32*j]; }
        #pragma unroll
        for(int r=0;r<4;r++){
            const int row = th*16 + wid*4 + r;
            float p = 0.f;
            #pragma unroll
            for(int j=0;j<8;j++){
                float h = geluf(red2(acc[r][j]));
                p += Xs[(wid*4+r)*SA + tx + 32*j]*wk[j] + h*wv[j];
            }
            p = warp_sum(p);
            if(tx==0){
                if(si==0){ float sp = (p>20.f)? p : log1pf(expf(p)); SC_eta[b][row] = sp*0.001f; }
                else       SC_alpha[b][row] = 1.f/(1.f+expf(-p));
            }
        }
    }
}

// ---------------- K2: per-token update terms + output (grid 224 x 128thr) ----------------
__global__ void __launch_bounds__(128) k2_token(float* __restrict__ dout, int chunk){
    extern __shared__ float sm[];
    const int tid = threadIdx.x, wid = tid>>5, tx = tid&31;
    const int bx = blockIdx.x, cur = chunk&1;

    if(bx < 128){
        float* Ks = sm;
        float* Hs = sm + XTILE;
        float* Gs = sm + 2*XTILE;
        float* Bt = sm + 3*XTILE;
        const int th = bx&3, f = (bx>>2)&3, b = bx>>4;
        const int s = (f==3)? 5 : f;

        load_tile16(Ks, SC_k[b] + th*16*DD);
        __syncthreads();

        u64 acc[4][8]; float zreg[4][8];
        gemmTB(Ks, S_w2[cur][s][b], Bt, acc);
        #pragma unroll
        for(int r=0;r<4;r++)
            #pragma unroll
            for(int j=0;j<8;j++){
                float z = red2(acc[r][j]); zreg[r][j] = z;
                float h = geluf(z);
                Hs[(wid*4+r)*SA + tx + 32*j] = h;
                SC_h2[s][b][(th*16 + wid*4 + r)*DD + tx + 32*j] = h;
            }
        gemmTB(Hs, S_w1f[cur][f][b], Bt, acc);
        #pragma unroll
        for(int r=0;r<4;r++)
            #pragma unroll
            for(int j=0;j<8;j++){
                const int row = th*16 + wid*4 + r, col = tx + 32*j;
                float g = 2.f*(Ks[(wid*4+r)*SA + col] + red2(acc[r][j]) - SC_v[b][row*DD+col]);
                Gs[(wid*4+r)*SA + col] = g;
                SC_g[f][b][row*DD+col] = g;
                Ks[(wid*4+r)*SA + col] = dgeluf(zreg[r][j]);  // repurpose Ks as dgelu tile
            }
        u64 accN[4][4];
        gemmN(Gs, S_w1f[cur][f][b], Bt, accN);
        #pragma unroll
        for(int r=0;r<4;r++){
            const int row = th*16 + wid*4 + r;
            #pragma unroll
            for(int p=0;p<4;p++){
                float2 v = up2(accN[r][p]);
                const int c0 = 2*tx + 64*p;
                SC_pre[s][b][row*DD + c0]     = v.x * Ks[(wid*4+r)*SA + c0];
                SC_pre[s][b][row*DD + c0 + 1] = v.y * Ks[(wid*4+r)*SA + c0 + 1];
            }
        }
    } else if(bx < 192){
        float* Ks = sm;
        float* Bt = sm + XTILE;
        const int i = bx-128, th = i&3, si = (i>>2)&1, b = i>>3;
        const int s = 3+si;

        load_tile16(Ks, SC_k[b] + th*16*DD);
        __syncthreads();

        u64 acc[4][8];
        gemmTB(Ks, S_w2[cur][s][b], Bt, acc);
        const float* wsk = S_wsk[cur][si][b];
        const float* w1v = S_w1v[cur][si][b];
        float wk[8], wv[8];
        #pragma unroll
        for(int j=0;j<8;j++){ wk[j] = wsk[tx+32*j]; wv[j] = w1v[tx+32*j]; }
        #pragma unroll
        for(int r=0;r<4;r++){
            const int row = th*16 + wid*4 + r;
            float hr[8], zr[8]; float p = 0.f;
            #pragma unroll
            for(int j=0;j<8;j++){
                float z = red2(acc[r][j]); zr[j] = z;
                float h = geluf(z); hr[j] = h;
                SC_h2[s][b][row*DD + tx + 32*j] = h;
                p += Ks[(wid*4+r)*SA + tx + 32*j]*wk[j] + h*wv[j];
            }
            p = warp_sum(p);
            float g = 2.f*(256.f*p - SC_vsum[b][row]);
            if(tx==0) SC_gs[si][b][row] = g;
            #pragma unroll
            for(int j=0;j<8;j++)
                SC_pre[s][b][row*DD + tx + 32*j] = g * wv[j] * dgeluf(zr[j]);
        }
    } else {
        float* Qs = sm;
        float* Hs = sm + XTILE;
        float* Bt = sm + 2*XTILE;
        const int i = bx-192, th = i&3, b = i>>2;

        load_tile16(Qs, SC_q[b] + th*16*DD);
        __syncthreads();

        u64 acc[4][8];
        gemmTB(Qs, S_w2[cur][5][b], Bt, acc);
        #pragma unroll
        for(int r=0;r<4;r++)
            #pragma unroll
            for(int j=0;j<8;j++)
                Hs[(wid*4+r)*SA + tx + 32*j] = geluf(red2(acc[r][j]));
        gemmTB(Hs, S_w1f[cur][3][b], Bt, acc);
        #pragma unroll
        for(int r=0;r<4;r++)
            #pragma unroll
            for(int j=0;j<8;j++){
                size_t off = ((size_t)b*TLEN + (size_t)chunk*CHK + th*16 + wid*4 + r)*DD + tx + 32*j;
                dout[off] = Qs[(wid*4+r)*SA + tx + 32*j] + red2(acc[r][j]);
            }
        if(th==0 && tid==0){
            float p = 1.f;
            #pragma unroll
            for(int t=0;t<CHK;t++) p *= SC_alpha[b][t];
            SC_abar[b] = p;
        }
    }
}

// ---------------- K3: weight updates (grid 656 x 256thr) ----------------
// Tile: 64 out-rows x 128 cols, K=64, rows-packed f32x2.
__global__ void __launch_bounds__(256) k3_weights(int chunk){
    extern __shared__ float sm[];
    float* Ges = sm;            // 64 x 66
    float* Bs  = sm + 64*66;    // 64 x 132
    const int tid = threadIdx.x, wid = tid>>5, tx = tid&31;
    const int bx = blockIdx.x;
    const int cur = chunk&1, nxt = cur^1;

    if(bx < 640){
        int b, ot, ch;
        const float *A, *Bsrc, *Wold; float* Wnew;
        if(bx < 512){
            b = bx>>6; int r = bx&63;
            int f = r>>4, m = (r>>3)&1; ot = (r>>1)&3; ch = r&1;
            int s = (f==3)? 5 : f;
            if(m==0){ A = SC_g[f][b];   Bsrc = SC_h2[s][b]; Wold = S_w1f[cur][f][b]; Wnew = S_w1f[nxt][f][b]; }
            else    { A = SC_pre[s][b]; Bsrc = SC_k[b];     Wold = S_w2[cur][s][b];  Wnew = S_w2[nxt][s][b]; }
        } else {
            int i = bx-512; b = i>>4; int r = i&15;
            int si = r>>3; ot = (r>>1)&3; ch = r&1;
            int s = 3+si;
            A = SC_pre[s][b]; Bsrc = SC_k[b]; Wold = S_w2[cur][s][b]; Wnew = S_w2[nxt][s][b];
        }
        const float abar = SC_abar[b];
        const float* eta = SC_eta[b];

        // stage B cols [ch*128, +128)
        #pragma unroll
        for(int l=0;l<8;l++){
            int idx = tid + l*256;           // 2048 float4s
            int t = idx>>5, qc = (idx&31)<<2;
            *reinterpret_cast<float4*>(Bs + t*132 + qc) =
                *reinterpret_cast<const float4*>(Bsrc + t*DD + ch*128 + qc);
        }
        // stage Ges[t][o] = A[t, ot*64+o] * eta[t]
        #pragma unroll
        for(int l=0;l<4;l++){
            int idx = tid + l*256;           // 1024 float4s
            int t = idx>>4, oq = (idx&15)<<2;
            float e = eta[t];
            float4 v = *reinterpret_cast<const float4*>(A + t*DD + ot*64 + oq);
            float2* p = reinterpret_cast<float2*>(Ges + t*66 + oq);
            p[0] = make_float2(v.x*e, v.y*e);
            p[1] = make_float2(v.z*e, v.w*e);
        }
        __syncthreads();

        u64 acc[4][4];
        #pragma unroll
        for(int rp=0;rp<4;rp++)
            #pragma unroll
            for(int j=0;j<4;j++) acc[rp][j] = 0ull;

        #pragma unroll 4
        for(int t=0;t<64;t++){
            u64 a[4];
            #pragma unroll
            for(int rp=0;rp<4;rp++)
                a[rp] = *reinterpret_cast<const u64*>(Ges + t*66 + wid*8 + 2*rp);
            float4 bv = *reinterpret_cast<const float4*>(Bs + t*132 + tx*4);
            u64 b0 = pk2(bv.x,bv.x), b1 = pk2(bv.y,bv.y), b2 = pk2(bv.z,bv.z), b3 = pk2(bv.w,bv.w);
            #pragma unroll
            for(int rp=0;rp<4;rp++){
                fmaX2(acc[rp][0], a[rp], b0);
                fmaX2(acc[rp][1], a[rp], b1);
                fmaX2(acc[rp][2], a[rp], b2);
                fmaX2(acc[rp][3], a[rp], b3);
            }
        }
        #pragma unroll
        for(int rp=0;rp<4;rp++){
            const int row0 = ot*64 + wid*8 + 2*rp;
            size_t off0 = (size_t)row0*DD + ch*128 + tx*4;
            float4 w0 = *reinterpret_cast<const float4*>(Wold + off0);
            float4 w1 = *reinterpret_cast<const float4*>(Wold + off0 + DD);
            float2 c0 = up2(acc[rp][0]), c1 = up2(acc[rp][1]);
            float2 c2 = up2(acc[rp][2]), c3 = up2(acc[rp][3]);
            float4 o0 = make_float4(abar*w0.x - c0.x, abar*w0.y - c1.x,
                                    abar*w0.z - c2.x, abar*w0.w - c3.x);
            float4 o1 = make_float4(abar*w1.x - c0.y, abar*w1.y - c1.y,
                                    abar*w1.z - c2.y, abar*w1.w - c3.y);
            *reinterpret_cast<float4*>(Wnew + off0)      = o0;
            *reinterpret_cast<float4*>(Wnew + off0 + DD) = o1;
        }
    } else {
        const int i = bx-640, b = i>>1, si = i&1, s = 3+si;
        const float abar = SC_abar[b];
        const int j = tid;
        float aA = 0.f, aB = 0.f;
        #pragma unroll 4
        for(int t=0;t<CHK;t++){
            float ge = SC_gs[si][b][t]*SC_eta[b][t];
            aA += ge * SC_h2[s][b][t*DD + j];
            aB += ge * SC_k[b][t*DD + j];
        }
        S_w1v[nxt][si][b][j] = abar*S_w1v[cur][si][b][j] - aA;
        S_wsk[nxt][si][b][j] = abar*S_wsk[cur][si][b][j] - aB;
    }
}

// ---------------- launch ----------------
#define SMEM1 ((2*XTILE + BTBUF)*4)      // 68096 B
#define SMEM2 ((3*XTILE + BTBUF)*4)      // 84736 B
#define SMEM3 ((64*66 + 64*132)*4)       // 50688 B

extern "C" void kernel_launch(void* const* d_in, const int* in_sizes, int n_in,
                              void* d_out, int out_size){
    (void)in_sizes; (void)n_in; (void)out_size;
    const float* x   = (const float*)d_in[0];
    const float* k1w = (const float*)d_in[1];
    const float* k2w = (const float*)d_in[2];
    const float* v1w = (const float*)d_in[3];
    const float* v2w = (const float*)d_in[4];
    const float* q1w = (const float*)d_in[5];
    const float* q2w = (const float*)d_in[6];
    const float* e1w = (const float*)d_in[7];
    const float* e2w = (const float*)d_in[8];
    const float* esw = (const float*)d_in[9];
    const float* a1w = (const float*)d_in[10];
    const float* a2w = (const float*)d_in[11];
    const float* asw = (const float*)d_in[12];
    const float* m1w = (const float*)d_in[13];
    const float* m2w = (const float*)d_in[14];
    float* out = (float*)d_out;

    cudaFuncSetAttribute(k1_forward, cudaFuncAttributeMaxDynamicSharedMemorySize, SMEM1);
    cudaFuncSetAttribute(k2_token,   cudaFuncAttributeMaxDynamicSharedMemorySize, SMEM2);
    cudaFuncSetAttribute(k3_weights, cudaFuncAttributeMaxDynamicSharedMemorySize, SMEM3);

    k0_init<<<dim3(DD*DD/256, 11), 256>>>(k1w,k2w,v1w,v2w,q1w,q2w,e1w,e2w,esw,a1w,a2w,asw,m1w,m2w);

    for(int c=0;c<NC;c++){
        k1_forward<<<160, 128, SMEM1>>>(x, c);
        k2_token  <<<224, 128, SMEM2>>>(out, c);
        k3_weights<<<656, 256, SMEM3>>>(c);
    }
}